// round 11
// baseline (speedup 1.0000x reference)
#include <cuda_runtime.h>

#define NTH   1024      // threads per block
#define NMAX  128       // max targets (n <= 100)
#define MMAX  320       // max proposals (m <= 300)
#define CAP   24        // per-row edge slot capacity (deg(IoU>0.5) << 24)
#define FULLMASK 0xffffffffu
#define IINF  0x7fffffff

// device globals (no allocation allowed); zero-initialized at load and
// re-zeroed by the solver block at the end of every run (replay-safe).
__device__ int   g_done = 0;
__device__ int   g_deg[NMAX];
__device__ int   g_colhas[MMAX];
__device__ short g_ecol[NMAX * CAP];
__device__ int   g_ewq[NMAX * CAP];

// Quantize w = C + 0.5 (C = -iou, iou fp32 in (0.5,1]) at scale 2^24.
// Both fp32 ops are EXACT (w is a multiple of 2^-24, |w| < 0.5), so the
// whole solver runs in exact integer arithmetic.
__device__ __forceinline__ int quantw(float cw) {
    return __float2int_rn(__fmul_rn(__fadd_rn(cw, 0.5f), 16777216.0f));
}

// Fused kernel: IoU blocks emit solver-ready per-row edge slots; one
// dedicated solver block pre-initializes, waits, then runs greedy JV init +
// exact integer SSP min-cost matching with aggregated dummy sink (provably
// equivalent to lap.lapjv(C, cost_limit=-0.5, extend_cost=True) restricted to
// real pairs; optimum unique a.s.; tie-breaks immaterial under uniqueness).
__global__ void __launch_bounds__(NTH, 1)
matcher_kernel(const float* __restrict__ tgt, const float* __restrict__ prp,
               int n, int m, float* __restrict__ out) {
    __shared__ short s_ecol[NMAX * CAP];
    __shared__ int   s_ewq[NMAX * CAP];
    __shared__ int   s_deg[NMAX];
    __shared__ unsigned char s_colhas[MMAX];
    __shared__ short colmap[MMAX], cinv[MMAX];
    __shared__ short rowlist[NMAX], bestcol[NMAX];
    __shared__ int   rc4i[MMAX];      // greedy column-claim (atomicMin)
    __shared__ int   u[NMAX], v[MMAX], spc[MMAX];
    __shared__ short path[MMAX], row4col[MMAX];
    __shared__ short col4row[NMAX];
    __shared__ unsigned char SC[MMAX];
    __shared__ short srl[NMAX];       // scanned rows, in order
    __shared__ short scl[MMAX];       // selected columns, in order
    __shared__ int   scv[MMAX];       // their labels at selection time
    __shared__ int s_nr, s_mp;

    const int tid = threadIdx.x;
    const int nio = (int)gridDim.x - 1;          // # IoU blocks

    if ((int)blockIdx.x < nio) {
        // ---- IoU block: exact fp32 IoU for this slice (1 pair/thread) ----
        const int nm = n * m;
        int idx = blockIdx.x * NTH + tid;
        if (idx < nm) {
            int i = idx / m, j = idx - i * m;
            float4 a = __ldg((const float4*)(tgt) + i);   // [x0,y0,x1,y1]
            float4 b = __ldg((const float4*)(prp) + j);

            // round-to-nearest intrinsics block FMA contraction: exact ref bits
            float area_a = __fmul_rn(__fsub_rn(a.z, a.x), __fsub_rn(a.w, a.y));
            float area_b = __fmul_rn(__fsub_rn(b.z, b.x), __fsub_rn(b.w, b.y));
            float ltx = fmaxf(a.x, b.x), lty = fmaxf(a.y, b.y);
            float rbx = fminf(a.z, b.z), rby = fminf(a.w, b.w);
            float wx = fmaxf(__fsub_rn(rbx, ltx), 0.0f);
            float wy = fmaxf(__fsub_rn(rby, lty), 0.0f);
            float inter = __fmul_rn(wx, wy);
            float uni = __fsub_rn(__fadd_rn(area_a, area_b), inter);
            float iou = __fdiv_rn(inter, uni);

            // only IoU>0.5 pairs can appear in the padded lapjv optimum;
            // write straight into solver-ready per-row slots
            if (iou > 0.5f) {
                int s = atomicAdd(&g_deg[i], 1);
                if (s < CAP) {
                    g_ecol[i * CAP + s] = (short)j;
                    g_ewq[i * CAP + s] = quantw(-iou);
                }
                g_colhas[j] = 1;
            }
        }
        __threadfence();                       // publish edge writes
        __syncthreads();
        if (tid == 0) atomicAdd(&g_done, 1);
        return;
    }

    // =========== dedicated solver block ===========
    // pre-initialize edge-independent state (overlaps with IoU blocks)
    for (int x = tid; x < m; x += NTH) { rc4i[x] = IINF; v[x] = 0; }
    for (int x = tid; x < n + m; x += NTH) out[x] = -1.0f;  // defaults
    __syncthreads();

    // wait for all IoU blocks (single wave: 31 blocks << #SMs, no deadlock)
    if (tid == 0) {
        volatile int* vd = &g_done;
        while (*vd != nio) { }
    }
    __syncthreads();
    __threadfence();                       // acquire all blocks' writes

    // ---- one straight parallel copy: globals -> shared (no decode) ----
    for (int x = tid; x < n; x += NTH) {
        int d = g_deg[x]; if (d > CAP) d = CAP;
        s_deg[x] = d;
    }
    for (int x = tid; x < m; x += NTH) s_colhas[x] = (unsigned char)g_colhas[x];
    for (int x = tid; x < n * CAP; x += NTH) {
        s_ecol[x] = g_ecol[x];
        s_ewq[x] = g_ewq[x];
    }
    __syncthreads();

    // ---- parallel compaction: warp 0 = columns, warp 1 = rows ----
    if (tid < 32) {
        int base = 0;
        for (int c = 0; c < m; c += 32) {
            int j = c + tid;
            bool f = (j < m) && s_colhas[j];
            unsigned mask = __ballot_sync(FULLMASK, f);
            int pos = base + __popc(mask & ((1u << tid) - 1));
            if (f) { cinv[j] = (short)pos; colmap[pos] = (short)j; }
            base += __popc(mask);
        }
        if (tid == 0) s_mp = base;
    } else if (tid < 64) {
        int lane = tid - 32;
        int rbase = 0;
        for (int c = 0; c < n; c += 32) {
            int i = c + lane;
            bool f = (i < n) && (s_deg[i] > 0);
            unsigned mask = __ballot_sync(FULLMASK, f);
            int rpos = rbase + __popc(mask & ((1u << lane) - 1));
            if (f) rowlist[rpos] = (short)i;
            rbase += __popc(mask);
        }
        if (lane == 0) s_nr = rbase;
    }
    // reset globals for the next graph replay (edges already in shared)
    __syncthreads();                       // copy done before reset
    for (int x = tid; x < n; x += NTH) g_deg[x] = 0;
    for (int x = tid; x < m; x += NTH) g_colhas[x] = 0;
    if (tid == 0) g_done = 0;
    const int mp = s_mp, nr = s_nr;

    // ---- exact integer SSP min-cost matching (warp 0) ----
    if (tid < 32) {
        // greedy JV init: u[i] = min_j w_ij (feasible: wq <= -1 so dummy
        // reduced cost -u[i] >= 0). Parallel column claim via atomicMin:
        // lowest row index wins (== sequential greedy in row order).
        for (int rr = tid; rr < nr; rr += 32) {
            int io = rowlist[rr];
            int d = s_deg[io], base = io * CAP;
            int bw = IINF; int bj = 0x7fff;
            for (int e = 0; e < d; ++e) {
                int w = s_ewq[base + e];
                int j = cinv[s_ecol[base + e]];
                if (w < bw || (w == bw && j < bj)) { bw = w; bj = j; }
            }
            u[rr] = bw;
            bestcol[rr] = (short)bj;
            atomicMin(&rc4i[bj], rr);
        }
        __syncwarp();
        for (int rr = tid; rr < nr; rr += 32) {
            int j = bestcol[rr];
            col4row[rr] = (rc4i[j] == rr) ? (short)j : (short)-1;
        }
        for (int x = tid; x < mp; x += 32) {
            int r = rc4i[x];
            row4col[x] = (r == IINF) ? (short)-1 : (short)r;
        }
        __syncwarp();

        for (int rr = 0; rr < nr; ++rr) {
            if (col4row[rr] >= 0) continue;   // satisfied by greedy init

            for (int x = tid; x < mp; x += 32) {
                spc[x] = IINF; SC[x] = 0;
            }
            __syncwarp();

            int i = rr;
            int shortest = 0;
            int spcD = IINF;                // aggregated dummy sink label
            int dpred = -1;
            int nsr = 0;                    // # scanned rows
            int sink = -1;
            int minVal = 0;
            bool dummySink = false;

            while (true) {
                if (tid == 0) srl[nsr] = (short)i;
                const int ui = u[i];

                // dummy ("stay unmatched") relax: w=0, v_dummy=0
                int dc = shortest - ui;
                if (dc < spcD) { spcD = dc; dpred = i; }

                // relax this row's edges (fixed-stride slots, shared)
                int io = rowlist[i];
                int d = s_deg[io], base = io * CAP;
                for (int e = tid; e < d; e += 32) {
                    int j = cinv[s_ecol[base + e]];
                    if (!SC[j]) {
                        int red = shortest + s_ewq[base + e] - ui - v[j];
                        if (red < spc[j]) { spc[j] = red; path[j] = (short)i; }
                    }
                }
                __syncwarp();

                // argmin over columns (scanned ones hold IINF); index
                // tie-break immaterial (optimum unique; IINF never wins:
                // finite dummy label is compared first)
                int best = IINF; int bidx = -1;
                for (int j = tid; j < mp; j += 32) {
                    int s = spc[j];
                    if (s < best) { best = s; bidx = j; }
                }
                int gmin = __reduce_min_sync(FULLMASK, best);

                if (spcD < gmin) { dummySink = true; minVal = spcD; nsr++; break; }
                unsigned who = __ballot_sync(FULLMASK, best == gmin);
                bidx = __shfl_sync(FULLMASK, bidx, __ffs(who) - 1);
                minVal = gmin;

                // record selection; mark scanned (all lanes write same values)
                SC[bidx] = 1;
                scl[nsr] = (short)bidx;
                scv[nsr] = gmin;
                spc[bidx] = IINF;            // excluded from future argmins
                nsr++;
                int r4 = row4col[bidx];
                if (r4 < 0) { sink = bidx; break; }
                i = r4;
                shortest = gmin;
            }
            __syncwarp();

            // O(steps) dual updates: row srl[t] was reached via column
            // scl[t-1] with label scv[t-1]; selected column scl[t] gets
            // v -= minVal - scv[t]. (JV form; dummy edges stay feasible.)
            for (int t = tid; t < nsr; t += 32) {
                int ii = srl[t];
                u[ii] += (t == 0) ? minVal : (minVal - scv[t - 1]);
            }
            int nsc = nsr - 1;               // selected columns (sink incl.)
            for (int t = tid; t < nsc; t += 32)
                v[scl[t]] -= minVal - scv[t];
            __syncwarp();

            // augment (lane 0, integer-only)
            if (tid == 0) {
                if (dummySink) {
                    int ii = dpred;
                    if (ii != rr) {
                        int j = col4row[ii];
                        col4row[ii] = -1;       // ii becomes unmatched
                        while (true) {
                            int i2 = path[j];
                            row4col[j] = (short)i2;
                            int nxt = col4row[i2];
                            col4row[i2] = (short)j;
                            j = nxt;
                            if (i2 == rr) break;
                        }
                    }
                } else {
                    int j = sink;
                    while (true) {
                        int i2 = path[j];
                        row4col[j] = (short)i2;
                        int nxt = col4row[i2];
                        col4row[i2] = (short)j;
                        j = nxt;
                        if (i2 == rr) break;
                    }
                }
            }
            __syncwarp();
        }
    }
    __syncthreads();

    // ---- matched outputs (defaults written above) ----
    for (int r = tid; r < nr; r += NTH) {
        int j = col4row[r];
        if (j >= 0) {
            int oi = rowlist[r], oj = colmap[j];
            out[oi] = (float)oj;
            out[n + oj] = (float)oi;
        }
    }
}

extern "C" void kernel_launch(void* const* d_in, const int* in_sizes, int n_in,
                              void* d_out, int out_size) {
    const float* tgt = (const float*)d_in[0];   // target_bbox   [N,4] fp32
    const float* prp = (const float*)d_in[1];   // proposal_bbox [M,4] fp32
    int N = in_sizes[0] / 4;
    int M = in_sizes[1] / 4;
    int nm = N * M;
    int blocks = (nm + NTH - 1) / NTH + 1;      // +1 dedicated solver block
    matcher_kernel<<<blocks, NTH>>>(tgt, prp, N, M, (float*)d_out);
}

// round 12
// speedup vs baseline: 1.0597x; 1.0597x over previous
#include <cuda_runtime.h>

#define NTH   1024      // threads per block
#define NMAX  128
#define MMAX  320
#define ECAP  2048      // shared-memory edge capacity
#define MAXE  30720     // >= n*m worst case
#define FULLMASK 0xffffffffu
#define IINF  0x7fffffff

// device globals (no allocation allowed); zero-initialized at load and
// re-zeroed by the solver block each run (replay-safe).
__device__ int   g_ne = 0;
__device__ int   g_done = 0;
__device__ int   g_eij[MAXE];
__device__ int   g_ewq[MAXE];
__device__ short g_ccol[MAXE];   // fallback CSR (E > ECAP)
__device__ int   g_cwq[MAXE];

// Quantize w = C + 0.5 (C = -iou, iou fp32 in (0.5,1]) at scale 2^24.
// Both fp32 ops are EXACT (w is a multiple of 2^-24, |w| < 0.5), so the
// whole solver runs in exact integer arithmetic.
__device__ __forceinline__ int quantw(float cw) {
    return __float2int_rn(__fmul_rn(__fadd_rn(cw, 0.5f), 16777216.0f));
}

// Fused kernel: IoU blocks emit quantized edges; one dedicated solver block
// pre-initializes, waits, then runs CSR build + greedy JV init + exact
// integer SSP min-cost matching (frontier Dijkstra) with aggregated dummy
// sink (provably equivalent to lap.lapjv(C, cost_limit=-0.5,
// extend_cost=True) restricted to real pairs; optimum unique a.s.).
__global__ void __launch_bounds__(NTH, 1)
matcher_kernel(const float* __restrict__ tgt, const float* __restrict__ prp,
               int n, int m, float* __restrict__ out) {
    __shared__ int   s_eij[ECAP];
    __shared__ int   s_ewq[ECAP];
    __shared__ short cs_col[ECAP];
    __shared__ int   cs_wq[ECAP];
    __shared__ int   cs_off[NMAX + 1];
    __shared__ int   deg[NMAX];
    __shared__ int   cur_off[NMAX];
    __shared__ unsigned char colhas[MMAX];
    __shared__ short colmap[MMAX], cinv[MMAX];
    __shared__ short rowlist[NMAX], bestcol[NMAX];
    __shared__ int   rc4i[MMAX];      // greedy column-claim (atomicMin)
    __shared__ int   u[NMAX], v[MMAX], spc[MMAX];
    __shared__ short path[MMAX], row4col[MMAX];
    __shared__ short col4row[NMAX];
    __shared__ unsigned char SC[MMAX];
    __shared__ short srl[NMAX];       // scanned rows, in order
    __shared__ short scl[MMAX];       // selected columns, in order
    __shared__ int   scv[MMAX];       // labels at selection time
    __shared__ short frq[MMAX];       // frontier: relaxed, unscanned columns
    __shared__ int   s_frn;
    __shared__ int s_nr, s_mp;

    const int tid = threadIdx.x;
    const int nio = (int)gridDim.x - 1;          // # IoU blocks

    if ((int)blockIdx.x < nio) {
        // ---- IoU block: exact fp32 IoU for this slice (1 pair/thread) ----
        const int nm = n * m;
        int idx = blockIdx.x * NTH + tid;
        if (idx < nm) {
            int i = idx / m, j = idx - i * m;
            float4 a = __ldg((const float4*)(tgt) + i);   // [x0,y0,x1,y1]
            float4 b = __ldg((const float4*)(prp) + j);

            // round-to-nearest intrinsics block FMA contraction: exact ref bits
            float area_a = __fmul_rn(__fsub_rn(a.z, a.x), __fsub_rn(a.w, a.y));
            float area_b = __fmul_rn(__fsub_rn(b.z, b.x), __fsub_rn(b.w, b.y));
            float ltx = fmaxf(a.x, b.x), lty = fmaxf(a.y, b.y);
            float rbx = fminf(a.z, b.z), rby = fminf(a.w, b.w);
            float wx = fmaxf(__fsub_rn(rbx, ltx), 0.0f);
            float wy = fmaxf(__fsub_rn(rby, lty), 0.0f);
            float inter = __fmul_rn(wx, wy);
            float uni = __fsub_rn(__fadd_rn(area_a, area_b), inter);
            float iou = __fdiv_rn(inter, uni);

            // only IoU>0.5 pairs can appear in the padded lapjv optimum
            if (iou > 0.5f) {
                int pos = atomicAdd(&g_ne, 1);
                if (pos < MAXE) {
                    g_eij[pos] = (i << 16) | j;
                    g_ewq[pos] = quantw(-iou);   // exact int weight
                }
            }
        }
        __threadfence();                       // publish edge writes
        __syncthreads();
        if (tid == 0) atomicAdd(&g_done, 1);
        return;
    }

    // =========== dedicated solver block ===========
    // pre-initialize edge-independent state (overlaps with IoU blocks)
    for (int x = tid; x < m; x += NTH) {
        colhas[x] = 0;
        rc4i[x] = IINF;
        v[x] = 0;
        spc[x] = IINF;    // one-time init; frontier reset keeps it clean
        SC[x] = 0;
    }
    for (int x = tid; x < n; x += NTH) deg[x] = 0;
    for (int x = tid; x < n + m; x += NTH) out[x] = -1.0f;  // defaults
    __syncthreads();

    // wait for all IoU blocks (single wave: 31 blocks << #SMs, no deadlock)
    if (tid == 0) {
        volatile int* vd = &g_done;
        while (*vd != nio) { }
    }
    __syncthreads();
    __threadfence();                       // acquire all blocks' writes

    int Eg = g_ne; if (Eg > MAXE) Eg = MAXE;
    const int E = Eg;
    const bool small = (E <= ECAP);

    // load edges to shared + histogram rows/flag cols
    for (int e = tid; e < E; e += NTH) {
        int pk = g_eij[e];
        int i = pk >> 16, j = pk & 0xffff;
        if (small) { s_eij[e] = pk; s_ewq[e] = g_ewq[e]; }
        atomicAdd(&deg[i], 1);
        colhas[j] = 1;
    }
    __syncthreads();

    // ---- parallel compaction: warp 0 = columns, warp 1 = rows + CSR offsets ----
    if (tid < 32) {
        int base = 0;
        for (int c = 0; c < m; c += 32) {
            int j = c + tid;
            bool f = (j < m) && colhas[j];
            unsigned mask = __ballot_sync(FULLMASK, f);
            int pos = base + __popc(mask & ((1u << tid) - 1));
            if (f) { cinv[j] = (short)pos; colmap[pos] = (short)j; }
            base += __popc(mask);
        }
        if (tid == 0) s_mp = base;
    } else if (tid < 64) {
        int lane = tid - 32;
        int rbase = 0, obase = 0;
        for (int c = 0; c < n; c += 32) {
            int i = c + lane;
            int d = (i < n) ? deg[i] : 0;
            bool f = d > 0;
            unsigned mask = __ballot_sync(FULLMASK, f);
            int rpos = rbase + __popc(mask & ((1u << lane) - 1));
            if (f) rowlist[rpos] = (short)i;
            rbase += __popc(mask);
            int incl = d;
            #pragma unroll
            for (int off = 1; off < 32; off <<= 1) {
                int t = __shfl_up_sync(FULLMASK, incl, off);
                if (lane >= off) incl += t;
            }
            int excl = obase + incl - d;
            if (i < n) { cs_off[i] = excl; cur_off[i] = excl; }
            obase += __shfl_sync(FULLMASK, incl, 31);
        }
        if (lane == 0) { s_nr = rbase; cs_off[n] = obase; }
    }
    __syncthreads();
    const int mp = s_mp, nr = s_nr;

    // ---- CSR scatter (compact col + already-quantized weight) ----
    if (small) {
        for (int e = tid; e < E; e += NTH) {
            int pk = s_eij[e]; int i = pk >> 16, j = pk & 0xffff;
            int p = atomicAdd(&cur_off[i], 1);
            cs_col[p] = cinv[j]; cs_wq[p] = s_ewq[e];
        }
    } else {
        for (int e = tid; e < E; e += NTH) {
            int pk = g_eij[e]; int i = pk >> 16, j = pk & 0xffff;
            int p = atomicAdd(&cur_off[i], 1);
            g_ccol[p] = cinv[j]; g_cwq[p] = g_ewq[e];
        }
    }
    __syncthreads();
    // globals fully consumed — reset now for the next graph replay
    if (tid == 0) { g_ne = 0; g_done = 0; }

    // ---- exact integer SSP min-cost matching (warp 0) ----
    if (tid < 32) {
        const short* Ccol = small ? cs_col : g_ccol;
        const int*   Cwq  = small ? cs_wq  : g_cwq;

        // greedy JV init: u[i] = min_j w_ij (feasible: wq <= -1 so dummy
        // reduced cost -u[i] >= 0). Parallel column claim via atomicMin.
        for (int rr = tid; rr < nr; rr += 32) {
            int io = rowlist[rr];
            int b = cs_off[io], e2 = cs_off[io + 1];
            int bw = IINF; int bj = 0x7fff;
            for (int e = b; e < e2; ++e) {
                int w = Cwq[e]; int j = Ccol[e];
                if (w < bw || (w == bw && j < bj)) { bw = w; bj = j; }
            }
            u[rr] = bw;
            bestcol[rr] = (short)bj;
            atomicMin(&rc4i[bj], rr);
        }
        __syncwarp();
        for (int rr = tid; rr < nr; rr += 32) {
            int j = bestcol[rr];
            col4row[rr] = (rc4i[j] == rr) ? (short)j : (short)-1;
        }
        for (int x = tid; x < mp; x += 32) {
            int r = rc4i[x];
            row4col[x] = (r == IINF) ? (short)-1 : (short)r;
        }
        __syncwarp();

        for (int rr = 0; rr < nr; ++rr) {
            if (col4row[rr] >= 0) continue;   // satisfied by greedy init

            if (tid == 0) s_frn = 0;
            __syncwarp();

            int i = rr;
            int shortest = 0;
            int spcD = IINF;                // aggregated dummy sink label
            int dpred = -1;
            int nsr = 0;                    // # scanned rows
            int sink = -1;
            int minVal = 0;
            bool dummySink = false;

            while (true) {
                if (tid == 0) srl[nsr] = (short)i;
                const int ui = u[i];

                // dummy ("stay unmatched") relax: w=0, v_dummy=0
                int dc = shortest - ui;
                if (dc < spcD) { spcD = dc; dpred = i; }

                // relax this row's edges; append first-touched columns to
                // the frontier (distinct columns per row => no duplicates)
                int io = rowlist[i];
                int b = cs_off[io], e2 = cs_off[io + 1];
                int base = shortest - ui;
                for (int e = b + tid; e < e2; e += 32) {
                    int j = Ccol[e];
                    if (!SC[j]) {
                        int red = base + Cwq[e] - v[j];
                        int old = spc[j];
                        if (red < old) {
                            spc[j] = red; path[j] = (short)i;
                            if (old == IINF) {
                                int p = atomicAdd(&s_frn, 1);
                                frq[p] = (short)j;
                            }
                        }
                    }
                }
                __syncwarp();
                int frn = s_frn;

                // argmin over the (small) frontier; scanned entries hold IINF
                int best = IINF; int bidx = -1;
                for (int t = tid; t < frn; t += 32) {
                    int j = frq[t];
                    int s = spc[j];
                    if (s < best) { best = s; bidx = j; }
                }
                int gmin = __reduce_min_sync(FULLMASK, best);

                if (spcD < gmin) { dummySink = true; minVal = spcD; nsr++; break; }
                unsigned who = __ballot_sync(FULLMASK, best == gmin);
                bidx = __shfl_sync(FULLMASK, bidx, __ffs(who) - 1);
                minVal = gmin;

                // record selection; mark scanned (all lanes write same values)
                SC[bidx] = 1;
                scl[nsr] = (short)bidx;
                scv[nsr] = gmin;
                spc[bidx] = IINF;            // excluded from future argmins
                nsr++;
                int r4 = row4col[bidx];
                if (r4 < 0) { sink = bidx; break; }
                i = r4;
                shortest = gmin;
            }
            __syncwarp();

            // O(steps) dual updates (JV form; dummy edges stay feasible)
            for (int t = tid; t < nsr; t += 32) {
                int ii = srl[t];
                u[ii] += (t == 0) ? minVal : (minVal - scv[t - 1]);
            }
            int nsc = nsr - 1;               // selected columns (sink incl.)
            for (int t = tid; t < nsc; t += 32)
                v[scl[t]] -= minVal - scv[t];

            // frontier cleanup: restore spc/SC only for touched columns
            int frn = s_frn;
            for (int t = tid; t < frn; t += 32) {
                int j = frq[t];
                spc[j] = IINF; SC[j] = 0;
            }
            __syncwarp();

            // augment (lane 0, integer-only)
            if (tid == 0) {
                if (dummySink) {
                    int ii = dpred;
                    if (ii != rr) {
                        int j = col4row[ii];
                        col4row[ii] = -1;       // ii becomes unmatched
                        while (true) {
                            int i2 = path[j];
                            row4col[j] = (short)i2;
                            int nxt = col4row[i2];
                            col4row[i2] = (short)j;
                            j = nxt;
                            if (i2 == rr) break;
                        }
                    }
                } else {
                    int j = sink;
                    while (true) {
                        int i2 = path[j];
                        row4col[j] = (short)i2;
                        int nxt = col4row[i2];
                        col4row[i2] = (short)j;
                        j = nxt;
                        if (i2 == rr) break;
                    }
                }
            }
            __syncwarp();
        }
    }
    __syncthreads();

    // ---- matched outputs (defaults written above) ----
    for (int r = tid; r < nr; r += NTH) {
        int j = col4row[r];
        if (j >= 0) {
            int oi = rowlist[r], oj = colmap[j];
            out[oi] = (float)oj;
            out[n + oj] = (float)oi;
        }
    }
}

extern "C" void kernel_launch(void* const* d_in, const int* in_sizes, int n_in,
                              void* d_out, int out_size) {
    const float* tgt = (const float*)d_in[0];   // target_bbox   [N,4] fp32
    const float* prp = (const float*)d_in[1];   // proposal_bbox [M,4] fp32
    int N = in_sizes[0] / 4;
    int M = in_sizes[1] / 4;
    int nm = N * M;
    int blocks = (nm + NTH - 1) / NTH + 1;      // +1 dedicated solver block
    matcher_kernel<<<blocks, NTH>>>(tgt, prp, N, M, (float*)d_out);
}